// round 4
// baseline (speedup 1.0000x reference)
#include <cuda_runtime.h>

// Problem constants
static constexpr int   N_PTS   = 16384;
static constexpr int   C_DIM   = 16;
static constexpr int   H_DIM   = 32;
static constexpr int   KNN     = 9;
static constexpr float UPD_RATE = 1e-4f;

// Spatial grid: 64x64 over [-5,5]
static constexpr int   GG  = 64;
static constexpr float GB  = 5.0f;
static constexpr int   CAP = 128;
static constexpr float CS  = 2.0f * GB / GG;
static constexpr float INV_CS = GG / (2.0f * GB);

// Persistent-kernel shape: one block per SM, guaranteed co-resident.
static constexpr int NBLK = 148;
static constexpr int NTHR = 512;
static constexpr int NTOT = NBLK * NTHR;   // 75776 threads
static constexpr int NWRP = NTOT / 32;     // 2368 warps

// Scratch (device globals: allocation-free per harness rules)
__device__ __align__(16) float  g_x [N_PTS * C_DIM];
__device__ __align__(16) float  g_ha[N_PTS * H_DIM];
__device__ __align__(16) float  g_hb[N_PTS * H_DIM];
__device__ int    g_idx[N_PTS * KNN];
__device__ int    g_cnt[GG * GG];
__device__ float4 g_pts[GG * GG * CAP];    // (x, y, bitcast(id), 0)

// Grid barrier state (sense persists across graph replays; sense is read at
// kernel start so replays remain deterministic).
__device__ int      g_bar_count = 0;
__device__ unsigned g_bar_sense = 0;

__device__ __forceinline__ void gsync(unsigned& sense) {
    __syncthreads();
    ++sense;
    if (threadIdx.x == 0) {
        __threadfence();
        int v = atomicAdd(&g_bar_count, 1);
        if (v == NBLK - 1) {
            g_bar_count = 0;
            __threadfence();
            atomicExch(&g_bar_sense, sense);
        } else {
            while (*((volatile unsigned*)&g_bar_sense) != sense) __nanosleep(32);
        }
        __threadfence();
    }
    __syncthreads();
}

__device__ __forceinline__ int cell_coord(float v) {
    int c = (int)floorf((v + GB) * INV_CS);
    c = c < 0 ? 0 : c;
    c = c > GG - 1 ? GG - 1 : c;
    return c;
}

__device__ __forceinline__ void bin_insert(float px, float py, int id) {
    int b = cell_coord(py) * GG + cell_coord(px);
    int s = atomicAdd(&g_cnt[b], 1);
    if (s < CAP) g_pts[b * CAP + s] = make_float4(px, py, __int_as_float(id), 0.0f);
}

// ---------------------------------------------------------------------------
// Warp-per-query kNN with lane-parallel ring scan (one query's full pipeline).
__device__ __forceinline__ void knn_query(int q, int lane) {
    const float qx = g_x[q * C_DIM + 0];
    const float qy = g_x[q * C_DIM + 1];
    const int cx = cell_coord(qx);
    const int cy = cell_coord(qy);

    const float INF = __int_as_float(0x7f800000);
    float bd[KNN];
    int   bi[KNN];
#pragma unroll
    for (int p = 0; p < KNN; ++p) { bd[p] = INF; bi[p] = q; }

    auto process_pts = [&](int b, int cnt) {
        const float4* pp = &g_pts[b * CAP];
        for (int t = lane; t < cnt; t += 32) {
            float4 p = pp[t];
            float dx = qx - p.x;
            float dy = qy - p.y;
            float d2 = __fadd_rn(__fmul_rn(dx, dx), __fmul_rn(dy, dy));
            if (d2 < bd[KNN - 1]) {
                float cd = d2;
                int   ci = __float_as_int(p.z);
#pragma unroll
                for (int pos = 0; pos < KNN; ++pos) {
                    if (cd < bd[pos]) {
                        float tf = bd[pos]; bd[pos] = cd; cd = tf;
                        int   ti = bi[pos]; bi[pos] = ci; ci = ti;
                    }
                }
            }
        }
    };

    {   // r = 0
        int b = cy * GG + cx;
        int cnt = g_cnt[b];
        cnt = cnt < CAP ? cnt : CAP;
        process_pts(b, cnt);
    }

    for (int r = 1; r < GG; ++r) {
        int nc = 8 * r;
        for (int base = 0; base < nc; base += 32) {
            int i = base + lane;
            int xx = 0, yy = 0;
            bool ok = (i < nc);
            if (ok) {
                int side = 2 * r + 1;
                if (i < side)          { xx = cx - r + i;          yy = cy - r; }
                else if (i < 2 * side) { xx = cx - r + (i - side); yy = cy + r; }
                else {
                    int j = i - 2 * side;
                    int m = 2 * r - 1;
                    xx = (j < m) ? (cx - r) : (cx + r);
                    yy = cy - r + 1 + (j < m ? j : j - m);
                }
                ok = (xx >= 0) & (xx < GG) & (yy >= 0) & (yy < GG);
            }
            int b = yy * GG + xx;
            int cnt = 0;
            if (ok) {
                cnt = g_cnt[b];
                cnt = cnt < CAP ? cnt : CAP;
            }
            unsigned mask = __ballot_sync(0xffffffffu, cnt > 0);
            while (mask) {
                int s = __ffs(mask) - 1;
                mask &= mask - 1;
                int bb = __shfl_sync(0xffffffffu, b,   s);
                int cc = __shfl_sync(0xffffffffu, cnt, s);
                process_pts(bb, cc);
            }
        }
        // >= KNN warp-wide candidates within rim  =>  safe to stop.
        float rim = (float)r * CS;
        float rim2 = rim * rim;
        int c = 0;
#pragma unroll
        for (int p = 0; p < KNN; ++p) c += (bd[p] <= rim2) ? 1 : 0;
#pragma unroll
        for (int off = 16; off > 0; off >>= 1)
            c += __shfl_xor_sync(0xffffffffu, c, off);
        if (c >= KNN) break;
    }

    // Merge 32 sorted local lists -> global top-9.
#pragma unroll
    for (int sel = 0; sel < KNN; ++sel) {
        unsigned long long pack =
            ((unsigned long long)__float_as_uint(bd[0]) << 32) | (unsigned)bi[0];
        unsigned long long m = pack;
#pragma unroll
        for (int off = 16; off > 0; off >>= 1) {
            unsigned long long o = __shfl_xor_sync(0xffffffffu, m, off);
            m = o < m ? o : m;
        }
        unsigned matched = __ballot_sync(0xffffffffu, pack == m);
        if (lane == __ffs(matched) - 1) {
#pragma unroll
            for (int p = 0; p < KNN - 1; ++p) { bd[p] = bd[p + 1]; bi[p] = bi[p + 1]; }
            bd[KNN - 1] = INF;
            bi[KNN - 1] = q;
        }
        if (lane == 0) g_idx[q * KNN + sel] = (int)(unsigned)(m & 0xffffffffu);
    }
}

// ---------------------------------------------------------------------------
// One GCN layer phase: 4 sub-threads per node, reduce-scatter via shfl_xor.
template <int CIN, int COUT, bool RELU, bool UPD, bool ZERO, bool BINFILL, bool WOUT>
__device__ __forceinline__ void layer_phase(const float* __restrict__ hin,
                                            const float* __restrict__ sW,
                                            float* __restrict__ hout,
                                            float* __restrict__ out2,
                                            int gtid) {
    constexpr int CPT = CIN / 4;
    constexpr int HLF = COUT / 2;
    constexpr int QTR = COUT / 4;

    if (ZERO) {
        for (int i = gtid; i < GG * GG; i += NTOT) g_cnt[i] = 0;
    }

    int u = gtid;                 // 65536 units < NTOT: single pass
    if (u >= N_PTS * 4) return;
    int n   = u >> 2;
    int sub = u & 3;

    float agg[CPT];
#pragma unroll
    for (int c = 0; c < CPT; ++c) agg[c] = 0.0f;

    const int* ip = g_idx + n * KNN;
#pragma unroll
    for (int k = 0; k < KNN; ++k) {
        int nb = __ldg(&ip[k]);
        const float4* row = (const float4*)(hin + nb * CIN + sub * CPT);
#pragma unroll
        for (int c4 = 0; c4 < CPT / 4; ++c4) {
            float4 v = row[c4];
            agg[4 * c4 + 0] += v.x;
            agg[4 * c4 + 1] += v.y;
            agg[4 * c4 + 2] += v.z;
            agg[4 * c4 + 3] += v.w;
        }
    }
#pragma unroll
    for (int c = 0; c < CPT; ++c) agg[c] *= (1.0f / 9.0f);

    float acc[COUT];
#pragma unroll
    for (int j = 0; j < COUT; ++j) acc[j] = 0.0f;
#pragma unroll
    for (int cl = 0; cl < CPT; ++cl) {
        float a = agg[cl];
        const float* wrow = &sW[(sub * CPT + cl) * COUT];
#pragma unroll
        for (int j = 0; j < COUT; ++j) acc[j] = fmaf(a, wrow[j], acc[j]);
    }

    bool b0 = (sub & 1) != 0;
    bool b1 = (sub & 2) != 0;
    float h1[HLF];
#pragma unroll
    for (int j = 0; j < HLF; ++j) {
        float keep = b0 ? acc[HLF + j] : acc[j];
        float send = b0 ? acc[j]       : acc[HLF + j];
        h1[j] = keep + __shfl_xor_sync(0xffffffffu, send, 1);
    }
    float h2[QTR];
#pragma unroll
    for (int j = 0; j < QTR; ++j) {
        float keep = b1 ? h1[QTR + j] : h1[j];
        float send = b1 ? h1[j]       : h1[QTR + j];
        h2[j] = keep + __shfl_xor_sync(0xffffffffu, send, 2);
    }
    int jbase = (b0 ? HLF : 0) + (b1 ? QTR : 0);

    float* outp = hout + n * COUT + jbase;
    float nx = 0.0f, ny = 0.0f;
#pragma unroll
    for (int v4 = 0; v4 < QTR / 4; ++v4) {
        float4 r;
        r.x = h2[4 * v4 + 0];
        r.y = h2[4 * v4 + 1];
        r.z = h2[4 * v4 + 2];
        r.w = h2[4 * v4 + 3];
        if (RELU) {
            r.x = fmaxf(r.x, 0.0f); r.y = fmaxf(r.y, 0.0f);
            r.z = fmaxf(r.z, 0.0f); r.w = fmaxf(r.w, 0.0f);
        }
        if (UPD) {
            float4 old = ((const float4*)outp)[v4];
            r.x = fmaf(r.x, UPD_RATE, old.x);
            r.y = fmaf(r.y, UPD_RATE, old.y);
            r.z = fmaf(r.z, UPD_RATE, old.z);
            r.w = fmaf(r.w, UPD_RATE, old.w);
        }
        ((float4*)outp)[v4] = r;
        if (WOUT) ((float4*)(out2 + n * COUT + jbase))[v4] = r;
        if (BINFILL && v4 == 0 && jbase == 0) { nx = r.x; ny = r.y; }
    }
    if (BINFILL && jbase == 0) bin_insert(nx, ny, n);
}

// ---------------------------------------------------------------------------
// The whole pipeline as one persistent kernel with grid barriers.
__global__ void __launch_bounds__(NTHR, 1)
k_fused(const float* __restrict__ seed,
        const float* __restrict__ W1, const float* __restrict__ W2,
        const float* __restrict__ W3, const float* __restrict__ W4,
        float* __restrict__ out) {
    __shared__ float sW1[C_DIM * H_DIM];
    __shared__ float sW2[H_DIM * H_DIM];
    __shared__ float sW3[H_DIM * H_DIM];
    __shared__ float sW4[H_DIM * C_DIM];

    const int tid  = threadIdx.x;
    const int gtid = blockIdx.x * NTHR + tid;
    const int gw   = gtid >> 5;
    const int lane = gtid & 31;

    unsigned sense = *((volatile unsigned*)&g_bar_sense);

    // -- init: stage weights, copy seed, zero counters --------------------
    for (int i = tid; i < C_DIM * H_DIM; i += NTHR) sW1[i] = W1[i];
    for (int i = tid; i < H_DIM * H_DIM; i += NTHR) sW2[i] = W2[i];
    for (int i = tid; i < H_DIM * H_DIM; i += NTHR) sW3[i] = W3[i];
    for (int i = tid; i < H_DIM * C_DIM; i += NTHR) sW4[i] = W4[i];
    {
        const float4* s4 = (const float4*)seed;
        float4*       x4 = (float4*)g_x;
        for (int i = gtid; i < (N_PTS * C_DIM) / 4; i += NTOT) x4[i] = s4[i];
        for (int i = gtid; i < GG * GG; i += NTOT) g_cnt[i] = 0;
    }
    gsync(sense);

    // -- step 0: binfill ---------------------------------------------------
    for (int i = gtid; i < N_PTS; i += NTOT)
        bin_insert(g_x[i * C_DIM + 0], g_x[i * C_DIM + 1], i);
    gsync(sense);

    // -- step 0: knn ---------------------------------------------------------
    for (int q = gw; q < N_PTS; q += NWRP) knn_query(q, lane);
    gsync(sense);

    // -- step 0: layers ------------------------------------------------------
    layer_phase<16, 32, true,  false, false, false, false>(g_x,  sW1, g_ha, nullptr, gtid);
    gsync(sense);
    layer_phase<32, 32, true,  false, false, false, false>(g_ha, sW2, g_hb, nullptr, gtid);
    gsync(sense);
    layer_phase<32, 32, true,  false, true,  false, false>(g_hb, sW3, g_ha, nullptr, gtid); // + zero cnt
    gsync(sense);
    layer_phase<32, 16, false, true,  false, true,  false>(g_ha, sW4, g_x,  nullptr, gtid); // x+= ; rebin
    gsync(sense);

    // -- step 1: knn ---------------------------------------------------------
    for (int q = gw; q < N_PTS; q += NWRP) knn_query(q, lane);
    gsync(sense);

    // -- step 1: layers ------------------------------------------------------
    layer_phase<16, 32, true,  false, false, false, false>(g_x,  sW1, g_ha, nullptr, gtid);
    gsync(sense);
    layer_phase<32, 32, true,  false, false, false, false>(g_ha, sW2, g_hb, nullptr, gtid);
    gsync(sense);
    layer_phase<32, 32, true,  false, false, false, false>(g_hb, sW3, g_ha, nullptr, gtid);
    gsync(sense);
    layer_phase<32, 16, false, true,  false, false, true >(g_ha, sW4, g_x,  out, gtid);     // x+= ; writeout
}

// ---------------------------------------------------------------------------
extern "C" void kernel_launch(void* const* d_in, const int* in_sizes, int n_in,
                              void* d_out, int out_size) {
    const float* seed = (const float*)d_in[0];
    const float* W1   = (const float*)d_in[1];
    const float* W2   = (const float*)d_in[2];
    const float* W3   = (const float*)d_in[3];
    const float* W4   = (const float*)d_in[4];

    k_fused<<<NBLK, NTHR>>>(seed, W1, W2, W3, W4, (float*)d_out);
}